// round 2
// baseline (speedup 1.0000x reference)
#include <cuda_runtime.h>

// Problem constants (fixed by the reference)
#define BB 16
#define SS 2048
#define HH 1024

// Folded projection vector u2[j] = sum_h v[h] * attn_w[h, H+j]
__device__ float g_u2[HH];

// ---------------------------------------------------------------------------
// Kernel 1: u2 = v^T @ attn_w[:, H:2H]
// 32 blocks x 512 threads. Block b owns columns j in [32b, 32b+32) — one full
// 128B line per row. 16 warps stride over h (lane <-> column), so every load
// is a fully-utilized coalesced 128B line. Cross-warp reduce in smem.
// Total unique traffic: 4 MB, perfectly coalesced. No atomics, no init.
// ---------------------------------------------------------------------------
__global__ __launch_bounds__(512) void u2_kernel(
    const float* __restrict__ attn_w,  // [H, 2H] row-major
    const float* __restrict__ v)       // [1, H]
{
    __shared__ float part[16][32];
    const int warp = threadIdx.x >> 5;   // 0..15
    const int lane = threadIdx.x & 31;
    const int j0 = blockIdx.x * 32;      // column tile base

    const float* base = attn_w + HH + j0 + lane;   // &W[0, H+j0+lane]
    float acc = 0.f;
#pragma unroll 4
    for (int h = warp; h < HH; h += 16) {
        acc += __ldg(v + h) * __ldg(base + (size_t)h * (2 * HH));
    }
    part[warp][lane] = acc;
    __syncthreads();

    if (threadIdx.x < 32) {
        float s = 0.f;
#pragma unroll
        for (int w = 0; w < 16; ++w) s += part[w][threadIdx.x];
        g_u2[j0 + threadIdx.x] = s;
    }
}

// ---------------------------------------------------------------------------
// Kernel 2: scores[row] = enc[row, :] . u2   for row in [0, B*S)
// warp-per-row, float4 vectorized with streaming (evict-first) loads on the
// 128 MB encoder tensor; u2 staged into shared once per block.
// ---------------------------------------------------------------------------
__global__ __launch_bounds__(256) void scores_kernel(
    const float* __restrict__ enc,    // [B, S, H]
    float* __restrict__ out)          // [B*S] scores (in d_out)
{
    __shared__ float4 su2[HH / 4];    // 4 KB
    su2[threadIdx.x] = reinterpret_cast<const float4*>(g_u2)[threadIdx.x];
    __syncthreads();

    const int warp = threadIdx.x >> 5;
    const int lane = threadIdx.x & 31;
    const int row  = blockIdx.x * 8 + warp;       // 0 .. B*S-1

    const float4* e = reinterpret_cast<const float4*>(enc) + (size_t)row * (HH / 4);

    float acc = 0.f;
#pragma unroll
    for (int it = 0; it < 8; ++it) {
        const float4 ev = __ldcs(e + it * 32 + lane);   // streaming: no reuse
        const float4 uv = su2[it * 32 + lane];
        acc += ev.x * uv.x + ev.y * uv.y + ev.z * uv.z + ev.w * uv.w;
    }
#pragma unroll
    for (int m = 16; m; m >>= 1)
        acc += __shfl_xor_sync(0xffffffffu, acc, m);
    if (lane == 0) out[row] = acc;
}

// ---------------------------------------------------------------------------
// Kernel 3: in-place row softmax over S=2048, one block per batch row.
// ---------------------------------------------------------------------------
__global__ __launch_bounds__(256) void softmax_kernel(float* __restrict__ out)
{
    __shared__ float red[8];
    float* row = out + (size_t)blockIdx.x * SS;
    const int tid  = threadIdx.x;
    const int warp = tid >> 5;
    const int lane = tid & 31;

    float x[8];
    float mx = -1e30f;
#pragma unroll
    for (int i = 0; i < 8; ++i) {
        x[i] = row[tid + i * 256];
        mx = fmaxf(mx, x[i]);
    }
#pragma unroll
    for (int m = 16; m; m >>= 1)
        mx = fmaxf(mx, __shfl_xor_sync(0xffffffffu, mx, m));
    if (lane == 0) red[warp] = mx;
    __syncthreads();
    float bmax = red[0];
#pragma unroll
    for (int i = 1; i < 8; ++i) bmax = fmaxf(bmax, red[i]);
    __syncthreads();

    float s = 0.f;
#pragma unroll
    for (int i = 0; i < 8; ++i) {
        x[i] = __expf(x[i] - bmax);
        s += x[i];
    }
#pragma unroll
    for (int m = 16; m; m >>= 1)
        s += __shfl_xor_sync(0xffffffffu, s, m);
    if (lane == 0) red[warp] = s;
    __syncthreads();
    float tot = 0.f;
#pragma unroll
    for (int i = 0; i < 8; ++i) tot += red[i];
    const float inv = 1.0f / tot;

#pragma unroll
    for (int i = 0; i < 8; ++i)
        row[tid + i * 256] = x[i] * inv;
}

// ---------------------------------------------------------------------------
// Inputs (metadata order): hidden [B,1,H], encoder_outputs [B,S,H],
//                          attn_w [H,2H], attn_b [H], v [1,H]
// hidden and attn_b are provably unused (softmax shift invariance folds them
// into a constant per row).
// Output: [B,1,S] float32.
// ---------------------------------------------------------------------------
extern "C" void kernel_launch(void* const* d_in, const int* in_sizes, int n_in,
                              void* d_out, int out_size)
{
    const float* enc    = (const float*)d_in[1];
    const float* attn_w = (const float*)d_in[2];
    const float* v      = (const float*)d_in[4];
    float* out = (float*)d_out;

    u2_kernel<<<HH / 32, 512>>>(attn_w, v);
    scores_kernel<<<(BB * SS) / 8, 256>>>(enc, out);
    softmax_kernel<<<BB, 256>>>(out);
}

// round 5
// speedup vs baseline: 1.2160x; 1.2160x over previous
#include <cuda_runtime.h>

// Problem constants (fixed by the reference)
#define BB 16
#define SS 2048
#define HH 1024

// Partial folded projection: g_u2p[c][j] = sum over h-chunk c of v[h]*W[h,H+j]
__device__ float g_u2p[8][HH];

// ---------------------------------------------------------------------------
// Kernel 1: partial u2 = v^T @ attn_w[:, H:2H], split over columns AND rows.
// grid (32, 8): blockIdx.x = 32-column tile, blockIdx.y = 128-row chunk.
// 256 threads = 8 warps; warp w covers rows {chunk+w, chunk+w+8, ...} (16 rows),
// lane <-> column, so each load is a fully-used coalesced 128B line and each
// warp has 16 independent loads in flight. 256 blocks spread over all SMs.
// ---------------------------------------------------------------------------
__global__ __launch_bounds__(256) void u2_kernel(
    const float* __restrict__ attn_w,  // [H, 2H] row-major
    const float* __restrict__ v)       // [1, H]
{
    __shared__ float part[8][32];
    const int warp = threadIdx.x >> 5;   // 0..7
    const int lane = threadIdx.x & 31;
    const int j0 = blockIdx.x * 32;      // column tile base
    const int h0 = blockIdx.y * 128;     // row chunk base

    const float* base = attn_w + HH + j0 + lane;   // &W[0, H+j0+lane]
    float acc = 0.f;
#pragma unroll
    for (int i = 0; i < 16; ++i) {
        const int h = h0 + warp + i * 8;
        acc += __ldg(v + h) * __ldg(base + (size_t)h * (2 * HH));
    }
    part[warp][lane] = acc;
    __syncthreads();

    if (threadIdx.x < 32) {
        float s = 0.f;
#pragma unroll
        for (int w = 0; w < 8; ++w) s += part[w][threadIdx.x];
        g_u2p[blockIdx.y][j0 + threadIdx.x] = s;
    }
}

// ---------------------------------------------------------------------------
// Kernel 2: scores[row] = enc[row, :] . u2   for row in [0, B*S)
// Stages u2 (summing the 8 h-chunk partials) into shared, then warp-per-row
// float4 dot with streaming loads on the 128 MB encoder tensor.
// ---------------------------------------------------------------------------
__global__ __launch_bounds__(256) void scores_kernel(
    const float* __restrict__ enc,    // [B, S, H]
    float* __restrict__ out)          // [B*S] scores (in d_out)
{
    __shared__ float4 su2[HH / 4];    // 4 KB
    {
        const float4* p = reinterpret_cast<const float4*>(g_u2p);  // [8][256]
        float4 a = p[threadIdx.x];
#pragma unroll
        for (int c = 1; c < 8; ++c) {
            const float4 b = p[c * (HH / 4) + threadIdx.x];
            a.x += b.x; a.y += b.y; a.z += b.z; a.w += b.w;
        }
        su2[threadIdx.x] = a;
    }
    __syncthreads();

    const int warp = threadIdx.x >> 5;
    const int lane = threadIdx.x & 31;
    const int row  = blockIdx.x * 8 + warp;       // 0 .. B*S-1

    const float4* e = reinterpret_cast<const float4*>(enc) + (size_t)row * (HH / 4);

    float acc = 0.f;
#pragma unroll
    for (int it = 0; it < 8; ++it) {
        const float4 ev = __ldcs(e + it * 32 + lane);   // streaming: no reuse
        const float4 uv = su2[it * 32 + lane];
        acc += ev.x * uv.x + ev.y * uv.y + ev.z * uv.z + ev.w * uv.w;
    }
#pragma unroll
    for (int m = 16; m; m >>= 1)
        acc += __shfl_xor_sync(0xffffffffu, acc, m);
    if (lane == 0) out[row] = acc;
}

// ---------------------------------------------------------------------------
// Kernel 3: in-place row softmax over S=2048, one block per batch row.
// ---------------------------------------------------------------------------
__global__ __launch_bounds__(256) void softmax_kernel(float* __restrict__ out)
{
    __shared__ float red[8];
    float* row = out + (size_t)blockIdx.x * SS;
    const int tid  = threadIdx.x;
    const int warp = tid >> 5;
    const int lane = tid & 31;

    float x[8];
    float mx = -1e30f;
#pragma unroll
    for (int i = 0; i < 8; ++i) {
        x[i] = row[tid + i * 256];
        mx = fmaxf(mx, x[i]);
    }
#pragma unroll
    for (int m = 16; m; m >>= 1)
        mx = fmaxf(mx, __shfl_xor_sync(0xffffffffu, mx, m));
    if (lane == 0) red[warp] = mx;
    __syncthreads();
    float bmax = red[0];
#pragma unroll
    for (int i = 1; i < 8; ++i) bmax = fmaxf(bmax, red[i]);
    __syncthreads();

    float s = 0.f;
#pragma unroll
    for (int i = 0; i < 8; ++i) {
        x[i] = __expf(x[i] - bmax);
        s += x[i];
    }
#pragma unroll
    for (int m = 16; m; m >>= 1)
        s += __shfl_xor_sync(0xffffffffu, s, m);
    if (lane == 0) red[warp] = s;
    __syncthreads();
    float tot = 0.f;
#pragma unroll
    for (int i = 0; i < 8; ++i) tot += red[i];
    const float inv = 1.0f / tot;

#pragma unroll
    for (int i = 0; i < 8; ++i)
        row[tid + i * 256] = x[i] * inv;
}

// ---------------------------------------------------------------------------
// Inputs (metadata order): hidden [B,1,H], encoder_outputs [B,S,H],
//                          attn_w [H,2H], attn_b [H], v [1,H]
// hidden and attn_b are provably unused (softmax shift invariance folds them
// into a constant per row).
// Output: [B,1,S] float32.
// ---------------------------------------------------------------------------
extern "C" void kernel_launch(void* const* d_in, const int* in_sizes, int n_in,
                              void* d_out, int out_size)
{
    const float* enc    = (const float*)d_in[1];
    const float* attn_w = (const float*)d_in[2];
    const float* v      = (const float*)d_in[4];
    float* out = (float*)d_out;

    dim3 g1(HH / 32, 8);
    u2_kernel<<<g1, 256>>>(attn_w, v);
    scores_kernel<<<(BB * SS) / 8, 256>>>(enc, out);
    softmax_kernel<<<BB, 256>>>(out);
}

// round 7
// speedup vs baseline: 1.2252x; 1.0076x over previous
#include <cuda_runtime.h>

// Problem constants (fixed by the reference)
#define BB 16
#define SS 2048
#define HH 1024

// Folded projection vector u2[j] = sum_h v[h] * attn_w[h, H+j].
// Invariant: zero at entry of every kernel_launch call. Zero-initialized at
// module load; softmax_kernel re-zeroes it at the end of every call, so the
// invariant holds across graph replays.
__device__ float g_u2[HH];

// ---------------------------------------------------------------------------
// Kernel 1: u2 += v^T @ attn_w[:, H:2H]  via REDG atomics.
// grid (8, 32): blockIdx.x = 128-column tile (32 lanes x float4),
//               blockIdx.y = 32-row h-chunk.
// 8 warps; warp w covers rows {h0+w, h0+w+8, h0+w+16, h0+w+24} — each row is
// one fully-coalesced 512B float4 line-pair. Block reduces in smem, then one
// warp atomicAdds 128 floats into g_u2 (~32 adds/address chip-wide).
// ---------------------------------------------------------------------------
__global__ __launch_bounds__(256) void u2_kernel(
    const float* __restrict__ attn_w,  // [H, 2H] row-major
    const float* __restrict__ v)       // [1, H]
{
    __shared__ float4 part[8][32];
    const int warp = threadIdx.x >> 5;   // 0..7
    const int lane = threadIdx.x & 31;
    const int j0 = blockIdx.x * 128;     // column tile base
    const int h0 = blockIdx.y * 32;      // row chunk base

    const float4* base = reinterpret_cast<const float4*>(attn_w + HH + j0) + lane;
    const size_t rstride = (2 * HH) / 4; // float4 stride per row

    float4 acc = make_float4(0.f, 0.f, 0.f, 0.f);
#pragma unroll
    for (int i = 0; i < 4; ++i) {
        const int h = h0 + warp + i * 8;
        const float vv = __ldg(v + h);
        const float4 w4 = __ldg(base + (size_t)h * rstride);
        acc.x += vv * w4.x; acc.y += vv * w4.y;
        acc.z += vv * w4.z; acc.w += vv * w4.w;
    }
    part[warp][lane] = acc;
    __syncthreads();

    if (warp == 0) {
        float4 s = part[0][lane];
#pragma unroll
        for (int w = 1; w < 8; ++w) {
            const float4 p = part[w][lane];
            s.x += p.x; s.y += p.y; s.z += p.z; s.w += p.w;
        }
        float* dst = g_u2 + j0 + lane * 4;
        atomicAdd(dst + 0, s.x);
        atomicAdd(dst + 1, s.y);
        atomicAdd(dst + 2, s.z);
        atomicAdd(dst + 3, s.w);
    }
}

// ---------------------------------------------------------------------------
// Kernel 2: scores[row] = enc[row, :] . u2   for row in [0, B*S)
// 512 threads = 16 warps, warp-per-row; u2 staged once per block (4 KB L2
// read). Streaming float4 loads on the 128 MB encoder tensor.
// ---------------------------------------------------------------------------
__global__ __launch_bounds__(512) void scores_kernel(
    const float* __restrict__ enc,    // [B, S, H]
    float* __restrict__ out)          // [B*S] scores (in d_out)
{
    __shared__ float4 su2[HH / 4];    // 4 KB
    if (threadIdx.x < HH / 4)
        su2[threadIdx.x] = reinterpret_cast<const float4*>(g_u2)[threadIdx.x];
    __syncthreads();

    const int warp = threadIdx.x >> 5;
    const int lane = threadIdx.x & 31;
    const int row  = blockIdx.x * 16 + warp;      // 0 .. B*S-1

    const float4* e = reinterpret_cast<const float4*>(enc) + (size_t)row * (HH / 4);

    float acc = 0.f;
#pragma unroll
    for (int it = 0; it < 8; ++it) {
        const float4 ev = __ldcs(e + it * 32 + lane);   // streaming: no reuse
        const float4 uv = su2[it * 32 + lane];
        acc += ev.x * uv.x + ev.y * uv.y + ev.z * uv.z + ev.w * uv.w;
    }
#pragma unroll
    for (int m = 16; m; m >>= 1)
        acc += __shfl_xor_sync(0xffffffffu, acc, m);
    if (lane == 0) out[row] = acc;
}

// ---------------------------------------------------------------------------
// Kernel 3: in-place row softmax over S=2048, one block per batch row.
// Also restores the g_u2 == 0 invariant for the next graph replay.
// ---------------------------------------------------------------------------
__global__ __launch_bounds__(256) void softmax_kernel(float* __restrict__ out)
{
    __shared__ float red[8];
    float* row = out + (size_t)blockIdx.x * SS;
    const int tid  = threadIdx.x;
    const int warp = tid >> 5;
    const int lane = tid & 31;

    // Reset g_u2 for the next call (runs after all scores blocks finished).
    if (blockIdx.x == 0)
        reinterpret_cast<float4*>(g_u2)[tid] = make_float4(0.f, 0.f, 0.f, 0.f);

    float x[8];
    float mx = -1e30f;
#pragma unroll
    for (int i = 0; i < 8; ++i) {
        x[i] = row[tid + i * 256];
        mx = fmaxf(mx, x[i]);
    }
#pragma unroll
    for (int m = 16; m; m >>= 1)
        mx = fmaxf(mx, __shfl_xor_sync(0xffffffffu, mx, m));
    if (lane == 0) red[warp] = mx;
    __syncthreads();
    float bmax = red[0];
#pragma unroll
    for (int i = 1; i < 8; ++i) bmax = fmaxf(bmax, red[i]);
    __syncthreads();

    float s = 0.f;
#pragma unroll
    for (int i = 0; i < 8; ++i) {
        x[i] = __expf(x[i] - bmax);
        s += x[i];
    }
#pragma unroll
    for (int m = 16; m; m >>= 1)
        s += __shfl_xor_sync(0xffffffffu, s, m);
    if (lane == 0) red[warp] = s;
    __syncthreads();
    float tot = 0.f;
#pragma unroll
    for (int i = 0; i < 8; ++i) tot += red[i];
    const float inv = 1.0f / tot;

#pragma unroll
    for (int i = 0; i < 8; ++i)
        row[tid + i * 256] = x[i] * inv;
}

// ---------------------------------------------------------------------------
// Inputs (metadata order): hidden [B,1,H], encoder_outputs [B,S,H],
//                          attn_w [H,2H], attn_b [H], v [1,H]
// hidden and attn_b are provably unused (softmax shift invariance folds them
// into a per-row constant).
// Output: [B,1,S] float32.
// ---------------------------------------------------------------------------
extern "C" void kernel_launch(void* const* d_in, const int* in_sizes, int n_in,
                              void* d_out, int out_size)
{
    const float* enc    = (const float*)d_in[1];
    const float* attn_w = (const float*)d_in[2];
    const float* v      = (const float*)d_in[4];
    float* out = (float*)d_out;

    dim3 g1(HH / 128, 32);
    u2_kernel<<<g1, 256>>>(attn_w, v);
    scores_kernel<<<(BB * SS) / 16, 512>>>(enc, out);
    softmax_kernel<<<BB, 256>>>(out);
}